// round 1
// baseline (speedup 1.0000x reference)
#include <cuda_runtime.h>
#include <cuda_bf16.h>
#include <math.h>

#define NN 4096
#define DD 256
#define KK 8
#define BM 128
#define BN 128
#define BK 16

// 64 MB sim buffer (zero-init static; allowed scratch per harness rules)
__device__ float g_sim[(size_t)NN * NN];
// per-row results: {row_loss, invalid_flag, pos_sum, neg_sum}
__device__ float4 g_row[NN];

// ---------------------------------------------------------------------------
// Kernel 1: symmetric tiled FFMA GEMM  sim = X * X^T
// grid (32,32); blocks with bc < br exit; off-diagonal blocks mirror-store.
// ---------------------------------------------------------------------------
__global__ void __launch_bounds__(256) gemm_sym(const float* __restrict__ X) {
    const int br = blockIdx.y, bc = blockIdx.x;
    if (bc < br) return;

    __shared__ float As[BK][BM];
    __shared__ float Bs[BK][BN];

    const int tid = threadIdx.x;
    const int tx = tid & 15;        // 0..15 -> columns
    const int ty = tid >> 4;        // 0..15 -> rows

    float acc[8][8];
    #pragma unroll
    for (int i = 0; i < 8; i++)
        #pragma unroll
        for (int j = 0; j < 8; j++) acc[i][j] = 0.f;

    const float4* X4 = (const float4*)X;

    for (int k0 = 0; k0 < DD; k0 += BK) {
        // load 128 rows x 16 k of A and B panels (512 float4 each, 2 per thread)
        #pragma unroll
        for (int it = 0; it < 2; it++) {
            int f   = tid + it * 256;      // 0..511
            int row = f >> 2;              // 0..127
            int kc  = f & 3;               // 0..3
            float4 va = X4[(size_t)(br * BM + row) * (DD / 4) + (k0 >> 2) + kc];
            As[kc * 4 + 0][row] = va.x;
            As[kc * 4 + 1][row] = va.y;
            As[kc * 4 + 2][row] = va.z;
            As[kc * 4 + 3][row] = va.w;
            float4 vb = X4[(size_t)(bc * BN + row) * (DD / 4) + (k0 >> 2) + kc];
            Bs[kc * 4 + 0][row] = vb.x;
            Bs[kc * 4 + 1][row] = vb.y;
            Bs[kc * 4 + 2][row] = vb.z;
            Bs[kc * 4 + 3][row] = vb.w;
        }
        __syncthreads();

        #pragma unroll
        for (int k = 0; k < BK; k++) {
            float a[8], b[8];
            float4 a0 = *(const float4*)&As[k][ty * 4];
            float4 a1 = *(const float4*)&As[k][64 + ty * 4];
            float4 b0 = *(const float4*)&Bs[k][tx * 4];
            float4 b1 = *(const float4*)&Bs[k][64 + tx * 4];
            a[0]=a0.x; a[1]=a0.y; a[2]=a0.z; a[3]=a0.w;
            a[4]=a1.x; a[5]=a1.y; a[6]=a1.z; a[7]=a1.w;
            b[0]=b0.x; b[1]=b0.y; b[2]=b0.z; b[3]=b0.w;
            b[4]=b1.x; b[5]=b1.y; b[6]=b1.z; b[7]=b1.w;
            #pragma unroll
            for (int i = 0; i < 8; i++)
                #pragma unroll
                for (int j = 0; j < 8; j++)
                    acc[i][j] = fmaf(a[i], b[j], acc[i][j]);
        }
        __syncthreads();
    }

    // ---- store tile (row-major) ----
    #pragma unroll
    for (int i = 0; i < 8; i++) {
        int r = br * BM + ((i < 4) ? (ty * 4 + i) : (64 + ty * 4 + i - 4));
        float4 c0 = make_float4(acc[i][0], acc[i][1], acc[i][2], acc[i][3]);
        float4 c1 = make_float4(acc[i][4], acc[i][5], acc[i][6], acc[i][7]);
        *(float4*)&g_sim[(size_t)r * NN + bc * BN + tx * 4]      = c0;
        *(float4*)&g_sim[(size_t)r * NN + bc * BN + 64 + tx * 4] = c1;
    }

    // ---- mirror store for off-diagonal tiles ----
    if (bc > br) {
        int rbase0 = br * BM + ty * 4;
        int rbase1 = br * BM + 64 + ty * 4;
        #pragma unroll
        for (int j = 0; j < 8; j++) {
            int c = bc * BN + ((j < 4) ? (tx * 4 + j) : (64 + tx * 4 + j - 4));
            float4 t0 = make_float4(acc[0][j], acc[1][j], acc[2][j], acc[3][j]);
            float4 t1 = make_float4(acc[4][j], acc[5][j], acc[6][j], acc[7][j]);
            *(float4*)&g_sim[(size_t)c * NN + rbase0] = t0;
            *(float4*)&g_sim[(size_t)c * NN + rbase1] = t1;
        }
    }
}

// ---------------------------------------------------------------------------
// helpers
// ---------------------------------------------------------------------------
__device__ __forceinline__ float softplus_f(float z) {
    // log(1+exp(z)), numerically stable
    return fmaxf(z, 0.f) + log1pf(__expf(-fabsf(z)));
}

__device__ __forceinline__ float block_red(float v, float* sh, bool is_min) {
    #pragma unroll
    for (int o = 16; o; o >>= 1) {
        float u = __shfl_xor_sync(0xffffffffu, v, o);
        v = is_min ? fminf(v, u) : (v + u);
    }
    int w = threadIdx.x >> 5, l = threadIdx.x & 31;
    __syncthreads();                 // protect scratch across back-to-back calls
    if (l == 0) sh[w] = v;
    __syncthreads();
    if (threadIdx.x < 32) {
        v = (l < 8) ? sh[l] : (is_min ? 1e30f : 0.f);
        #pragma unroll
        for (int o = 4; o; o >>= 1) {
            float u = __shfl_xor_sync(0xffffffffu, v, o);
            v = is_min ? fminf(v, u) : (v + u);
        }
        if (l == 0) sh[0] = v;
    }
    __syncthreads();
    return sh[0];
}

// ---------------------------------------------------------------------------
// Kernel 2: per-row stats + loss. One CTA (256 threads) per row.
// ---------------------------------------------------------------------------
__global__ void __launch_bounds__(256) rowstats() {
    const int i   = blockIdx.x;
    const int tid = threadIdx.x;

    __shared__ float srow[NN];       // 16 KB row cache
    __shared__ float red[32];
    __shared__ float s_inter, s_th;

    const float* rp = &g_sim[(size_t)i * NN];
    for (int j = tid; j < NN; j += 256)
        srow[j] = rp[j];
    __syncthreads();

    const int cls_lo = (i / KK) * KK;
    const int cls_hi = cls_lo + KK;

    // pass 1: stats
    float ps = 0.f, pq = 0.f, pmin = 1e30f, ns = 0.f, nq = 0.f;
    for (int j = tid; j < NN; j += 256) {
        float s = srow[j];
        bool same = (j >= cls_lo) & (j < cls_hi);
        if (same) {
            if (j != i) { ps += s; pq += s * s; pmin = fminf(pmin, s); }
        } else {
            ns += s; nq += s * s;
        }
    }
    ps   = block_red(ps, red, false);
    pq   = block_red(pq, red, false);
    ns   = block_red(ns, red, false);
    nq   = block_red(nq, red, false);
    pmin = block_red(pmin, red, true);

    if (tid == 0) {
        const float p = (float)(KK - 1);          // 7
        const float m = (float)(NN - KK);         // 4088
        float pmean = ps / p, nmean = ns / m;
        float pvar = fmaxf(pq / p - pmean * pmean, 0.f);
        float nvar = fmaxf(nq / m - nmean * nmean, 0.f);
        float psd = sqrtf(pvar), nsd = sqrtf(nvar);
        s_inter = 0.8f * (nsd * pmean + psd * nmean) / (psd + nsd) + 0.1f;
        s_th    = pmin - 0.05f;
    }
    __syncthreads();
    const float inter = s_inter;
    const float th    = s_th;

    // pass 2: losses
    float psum = 0.f, nsum = 0.f, cntf = 0.f;
    for (int j = tid; j < NN; j += 256) {
        float s = srow[j];
        bool same = (j >= cls_lo) & (j < cls_hi);
        if (same) {
            if (j != i) psum += softplus_f(-10.f * (s - inter));
        } else if (s > th) {
            cntf += 1.f;
            nsum += softplus_f(40.f * (s - inter));
        }
    }
    psum = block_red(psum, red, false);
    nsum = block_red(nsum, red, false);
    cntf = block_red(cntf, red, false);

    if (tid == 0) {
        float loss = 0.f, invalid = 1.f;
        if (cntf > 0.f) {
            loss = 0.2f * psum / (float)(KK - 1) + 0.05f * nsum / cntf;
            invalid = 0.f;
        }
        g_row[i] = make_float4(loss, invalid, ps, ns);
    }
}

// ---------------------------------------------------------------------------
// Kernel 3: deterministic final reduction over 4096 rows.
// ---------------------------------------------------------------------------
__global__ void __launch_bounds__(256) final_reduce(float* __restrict__ out) {
    __shared__ float red[32];
    const int tid = threadIdx.x;
    float a0 = 0.f, a1 = 0.f, a2 = 0.f, a3 = 0.f;
    for (int i = tid; i < NN; i += 256) {
        float4 v = g_row[i];
        a0 += v.x; a1 += v.y; a2 += v.z; a3 += v.w;
    }
    a0 = block_red(a0, red, false);
    a1 = block_red(a1, red, false);
    a2 = block_red(a2, red, false);
    a3 = block_red(a3, red, false);
    if (tid == 0) {
        out[0] = a0 / (float)NN;                                  // loss
        out[1] = a1 / (float)NN;                                  // prec
        out[2] = a2 / ((float)(KK - 1) * (float)NN);              // pos_d
        out[3] = a3 / ((float)(NN - KK) * (float)NN);             // neg_d
    }
}

// ---------------------------------------------------------------------------
extern "C" void kernel_launch(void* const* d_in, const int* in_sizes, int n_in,
                              void* d_out, int out_size) {
    const float* X = (const float*)d_in[0];
    float* out = (float*)d_out;

    dim3 grid_g(NN / BN, NN / BM);
    gemm_sym<<<grid_g, 256>>>(X);
    rowstats<<<NN, 256>>>();
    final_reduce<<<1, 256>>>(out);
}

// round 3
// speedup vs baseline: 1.7464x; 1.7464x over previous
#include <cuda_runtime.h>
#include <cuda_bf16.h>
#include <math.h>
#include <stdint.h>

#define NN 4096
#define DD 256
#define KK 8

// ---------------------------------------------------------------------------
// Scratch (static __device__, no allocs)
// ---------------------------------------------------------------------------
__device__ float g_sim[(size_t)NN * NN];                  // 64 MB
__device__ __nv_bfloat16 g_hi[(size_t)NN * DD];           // 2 MB
__device__ __nv_bfloat16 g_lo[(size_t)NN * DD];           // 2 MB
__device__ float4 g_row[NN];                              // per-row results

// ---------------------------------------------------------------------------
// helpers
// ---------------------------------------------------------------------------
__device__ __forceinline__ uint32_t smem_u32(const void* p) {
    uint32_t a;
    asm("{ .reg .u64 t; cvta.to.shared.u64 t, %1; cvt.u32.u64 %0, t; }"
        : "=r"(a) : "l"(p));
    return a;
}
#define SWZ128(x) ((x) ^ (((x) >> 3) & 0x70))

__device__ __forceinline__ void cp_async16(uint32_t saddr, const void* gaddr) {
    asm volatile("cp.async.cg.shared.global [%0], [%1], 16;"
                 :: "r"(saddr), "l"(gaddr) : "memory");
}
#define CP_COMMIT() asm volatile("cp.async.commit_group;" ::: "memory")
#define CP_WAIT(n)  asm volatile("cp.async.wait_group %0;" :: "n"(n) : "memory")

__device__ __forceinline__ void ldmat_x4(uint32_t& r0, uint32_t& r1,
                                         uint32_t& r2, uint32_t& r3, uint32_t a) {
    asm volatile("ldmatrix.sync.aligned.m8n8.x4.shared.b16 {%0,%1,%2,%3}, [%4];"
                 : "=r"(r0), "=r"(r1), "=r"(r2), "=r"(r3) : "r"(a));
}

__device__ __forceinline__ void mma_bf16(float* c, const uint32_t* a, const uint32_t* b) {
    asm volatile("mma.sync.aligned.m16n8k16.row.col.f32.bf16.bf16.f32 "
                 "{%0,%1,%2,%3}, {%4,%5,%6,%7}, {%8,%9}, {%0,%1,%2,%3};"
                 : "+f"(c[0]), "+f"(c[1]), "+f"(c[2]), "+f"(c[3])
                 : "r"(a[0]), "r"(a[1]), "r"(a[2]), "r"(a[3]),
                   "r"(b[0]), "r"(b[1]));
}

// ---------------------------------------------------------------------------
// Kernel 0: bf16 hi/lo split
// ---------------------------------------------------------------------------
__global__ void __launch_bounds__(256) split_bf16(const float* __restrict__ X) {
    int i = blockIdx.x * 256 + threadIdx.x;
    float x = X[i];
    __nv_bfloat16 h = __float2bfloat16(x);
    g_hi[i] = h;
    g_lo[i] = __float2bfloat16(x - __bfloat162float(h));
}

// ---------------------------------------------------------------------------
// Kernel 1: symmetric bf16x3 GEMM via mma.sync (HMMA), cp.async double-buffer.
// CTA: 128x128 tile, 8 warps (2 x 4), warp tile 64x32. K = 3*256 logical.
// ---------------------------------------------------------------------------
extern __shared__ unsigned char dynsmem[];   // 64 KB: 2 x (16K A + 16K B)

__global__ void __launch_bounds__(256, 2) gemm_mma() {
    const int br = blockIdx.y, bc = blockIdx.x;
    if (bc < br) return;

    const int tid = threadIdx.x;
    const int wid = tid >> 5, lid = tid & 31;
    const int wr = wid >> 2, wc = wid & 3;      // 2 x 4 warp grid

    const uint32_t sbase = smem_u32(dynsmem);

    float acc[4][4][4];
    #pragma unroll
    for (int mi = 0; mi < 4; mi++)
        #pragma unroll
        for (int ni = 0; ni < 4; ni++)
            #pragma unroll
            for (int q = 0; q < 4; q++) acc[mi][ni][q] = 0.f;

    // per-thread load slots: 4 iterations cover 1024 (row,seg) pairs
    int lrow[4], lsg[4];
    uint32_t soff[4];
    #pragma unroll
    for (int it = 0; it < 4; it++) {
        int idx = tid + it * 256;
        lrow[it] = idx >> 3;
        lsg[it]  = idx & 7;
        soff[it] = SWZ128((uint32_t)(lrow[it] * 128 + lsg[it] * 16));
    }

    const __nv_bfloat16* Asrc[3] = { g_hi, g_hi, g_lo };
    const __nv_bfloat16* Bsrc[3] = { g_hi, g_lo, g_hi };

    auto issue = [&](int c) {
        const int seg = c >> 2, colb = (c & 3) * 64;
        const char* pa = (const char*)Asrc[seg];
        const char* pb = (const char*)Bsrc[seg];
        const uint32_t sb = sbase + (uint32_t)(c & 1) * 32768u;
        #pragma unroll
        for (int it = 0; it < 4; it++) {
            size_t ao = ((size_t)(br * 128 + lrow[it]) * DD + colb) * 2 + lsg[it] * 16;
            size_t bo = ((size_t)(bc * 128 + lrow[it]) * DD + colb) * 2 + lsg[it] * 16;
            cp_async16(sb + soff[it], pa + ao);
            cp_async16(sb + 16384u + soff[it], pb + bo);
        }
        CP_COMMIT();
    };

    issue(0);

    for (int c = 0; c < 12; c++) {
        if (c + 1 < 12) { issue(c + 1); CP_WAIT(1); }
        else            { CP_WAIT(0); }
        __syncthreads();

        const uint32_t sA = sbase + (uint32_t)(c & 1) * 32768u;
        const uint32_t sB = sA + 16384u;
        const int sub = lid >> 3;          // ldmatrix matrix id
        const int l8  = lid & 7;

        #pragma unroll
        for (int kk = 0; kk < 4; kk++) {
            const int kbase = kk * 16;
            // --- B fragments: 4 n8 tiles x 2 regs ---
            uint32_t bfr[4][2];
            #pragma unroll
            for (int nj = 0; nj < 2; nj++) {
                int n  = wc * 32 + nj * 16 + l8 + (sub >> 1) * 8;
                int kh = kbase + (sub & 1) * 8;
                uint32_t addr = sB + SWZ128((uint32_t)(n * 128 + kh * 2));
                uint32_t r0, r1, r2, r3;
                ldmat_x4(r0, r1, r2, r3, addr);
                bfr[nj * 2 + 0][0] = r0; bfr[nj * 2 + 0][1] = r1;
                bfr[nj * 2 + 1][0] = r2; bfr[nj * 2 + 1][1] = r3;
            }
            // --- A fragments per m16 tile, then 4 mmas ---
            #pragma unroll
            for (int mi = 0; mi < 4; mi++) {
                int r  = wr * 64 + mi * 16 + l8 + (sub & 1) * 8;
                int kh = kbase + (sub >> 1) * 8;
                uint32_t addr = sA + SWZ128((uint32_t)(r * 128 + kh * 2));
                uint32_t afr[4];
                ldmat_x4(afr[0], afr[1], afr[2], afr[3], addr);
                #pragma unroll
                for (int ni = 0; ni < 4; ni++)
                    mma_bf16(acc[mi][ni], afr, bfr[ni]);
            }
        }
        __syncthreads();
    }

    // ----- direct stores (upper-triangle tile, row-major) -----
    const int qr = lid >> 2, qc = lid & 3;
    #pragma unroll
    for (int mi = 0; mi < 4; mi++) {
        int row = br * 128 + wr * 64 + mi * 16 + qr;
        #pragma unroll
        for (int ni = 0; ni < 4; ni++) {
            int col = bc * 128 + wc * 32 + ni * 8 + 2 * qc;
            *(float2*)&g_sim[(size_t)row * NN + col] =
                make_float2(acc[mi][ni][0], acc[mi][ni][1]);
            *(float2*)&g_sim[(size_t)(row + 8) * NN + col] =
                make_float2(acc[mi][ni][2], acc[mi][ni][3]);
        }
    }

    // ----- mirror stores via padded smem transpose -----
    if (bc > br) {
        float* tr = (float*)(dynsmem + 32768);   // 32 x 132 staging
        for (int cc = 0; cc < 4; cc++) {
            __syncthreads();
            if (wc == cc) {
                #pragma unroll
                for (int mi = 0; mi < 4; mi++) {
                    int r = wr * 64 + mi * 16 + qr;
                    #pragma unroll
                    for (int ni = 0; ni < 4; ni++) {
                        int j = ni * 8 + 2 * qc;
                        tr[(size_t)j * 132 + r]           = acc[mi][ni][0];
                        tr[(size_t)(j + 1) * 132 + r]     = acc[mi][ni][1];
                        tr[(size_t)j * 132 + r + 8]       = acc[mi][ni][2];
                        tr[(size_t)(j + 1) * 132 + r + 8] = acc[mi][ni][3];
                    }
                }
            }
            __syncthreads();
            for (int j = wid; j < 32; j += 8) {
                int gr = bc * 128 + cc * 32 + j;
                float4 v = *(float4*)&tr[(size_t)j * 132 + lid * 4];
                *(float4*)&g_sim[(size_t)gr * NN + br * 128 + lid * 4] = v;
            }
        }
    }
}

// ---------------------------------------------------------------------------
__device__ __forceinline__ float softplus_f(float z) {
    return fmaxf(z, 0.f) + log1pf(__expf(-fabsf(z)));
}

__device__ __forceinline__ float block_red(float v, float* sh, bool is_min) {
    #pragma unroll
    for (int o = 16; o; o >>= 1) {
        float u = __shfl_xor_sync(0xffffffffu, v, o);
        v = is_min ? fminf(v, u) : (v + u);
    }
    int w = threadIdx.x >> 5, l = threadIdx.x & 31;
    __syncthreads();
    if (l == 0) sh[w] = v;
    __syncthreads();
    if (threadIdx.x < 32) {
        v = (l < 8) ? sh[l] : (is_min ? 1e30f : 0.f);
        #pragma unroll
        for (int o = 4; o; o >>= 1) {
            float u = __shfl_xor_sync(0xffffffffu, v, o);
            v = is_min ? fminf(v, u) : (v + u);
        }
        if (l == 0) sh[0] = v;
    }
    __syncthreads();
    return sh[0];
}

// ---------------------------------------------------------------------------
// Kernel 2: per-row stats + loss; row held in 16 registers/thread.
// ---------------------------------------------------------------------------
__global__ void __launch_bounds__(256) rowstats() {
    const int i   = blockIdx.x;
    const int tid = threadIdx.x;

    __shared__ float red[32];
    __shared__ float s_inter, s_th;

    float v[16];
    const float4* rp = (const float4*)&g_sim[(size_t)i * NN];
    #pragma unroll
    for (int q = 0; q < 4; q++) {
        float4 t = rp[tid + q * 256];
        v[q * 4 + 0] = t.x; v[q * 4 + 1] = t.y;
        v[q * 4 + 2] = t.z; v[q * 4 + 3] = t.w;
    }

    const int cls_lo = (i / KK) * KK;
    const int cls_hi = cls_lo + KK;

    float ps = 0.f, pq = 0.f, pmin = 1e30f, ns = 0.f, nq = 0.f;
    #pragma unroll
    for (int q = 0; q < 4; q++) {
        #pragma unroll
        for (int s = 0; s < 4; s++) {
            int j = (tid + q * 256) * 4 + s;
            float x = v[q * 4 + s];
            bool same = (j >= cls_lo) & (j < cls_hi);
            if (same) {
                if (j != i) { ps += x; pq += x * x; pmin = fminf(pmin, x); }
            } else {
                ns += x; nq += x * x;
            }
        }
    }
    ps   = block_red(ps, red, false);
    pq   = block_red(pq, red, false);
    ns   = block_red(ns, red, false);
    nq   = block_red(nq, red, false);
    pmin = block_red(pmin, red, true);

    if (tid == 0) {
        const float p = (float)(KK - 1);
        const float m = (float)(NN - KK);
        float pmean = ps / p, nmean = ns / m;
        float pvar = fmaxf(pq / p - pmean * pmean, 0.f);
        float nvar = fmaxf(nq / m - nmean * nmean, 0.f);
        float psd = sqrtf(pvar), nsd = sqrtf(nvar);
        s_inter = 0.8f * (nsd * pmean + psd * nmean) / (psd + nsd) + 0.1f;
        s_th    = pmin - 0.05f;
    }
    __syncthreads();
    const float inter = s_inter;
    const float th    = s_th;

    float psum = 0.f, nsum = 0.f, cntf = 0.f;
    #pragma unroll
    for (int q = 0; q < 4; q++) {
        #pragma unroll
        for (int s = 0; s < 4; s++) {
            int j = (tid + q * 256) * 4 + s;
            float x = v[q * 4 + s];
            bool same = (j >= cls_lo) & (j < cls_hi);
            if (same) {
                if (j != i) psum += softplus_f(-10.f * (x - inter));
            } else if (x > th) {
                cntf += 1.f;
                nsum += softplus_f(40.f * (x - inter));
            }
        }
    }
    psum = block_red(psum, red, false);
    nsum = block_red(nsum, red, false);
    cntf = block_red(cntf, red, false);

    if (tid == 0) {
        float loss = 0.f, invalid = 1.f;
        if (cntf > 0.f) {
            loss = 0.2f * psum / (float)(KK - 1) + 0.05f * nsum / cntf;
            invalid = 0.f;
        }
        g_row[i] = make_float4(loss, invalid, ps, ns);
    }
}

// ---------------------------------------------------------------------------
// Kernel 3: deterministic final reduction
// ---------------------------------------------------------------------------
__global__ void __launch_bounds__(256) final_reduce(float* __restrict__ out) {
    __shared__ float red[32];
    const int tid = threadIdx.x;
    float a0 = 0.f, a1 = 0.f, a2 = 0.f, a3 = 0.f;
    for (int i = tid; i < NN; i += 256) {
        float4 v = g_row[i];
        a0 += v.x; a1 += v.y; a2 += v.z; a3 += v.w;
    }
    a0 = block_red(a0, red, false);
    a1 = block_red(a1, red, false);
    a2 = block_red(a2, red, false);
    a3 = block_red(a3, red, false);
    if (tid == 0) {
        out[0] = a0 / (float)NN;
        out[1] = a1 / (float)NN;
        out[2] = a2 / ((float)(KK - 1) * (float)NN);
        out[3] = a3 / ((float)(NN - KK) * (float)NN);
    }
}

// ---------------------------------------------------------------------------
extern "C" void kernel_launch(void* const* d_in, const int* in_sizes, int n_in,
                              void* d_out, int out_size) {
    const float* X = (const float*)d_in[0];
    float* out = (float*)d_out;

    static bool attr_set = false;
    if (!attr_set) {
        cudaFuncSetAttribute(gemm_mma, cudaFuncAttributeMaxDynamicSharedMemorySize, 65536);
        attr_set = true;
    }

    split_bf16<<<NN * DD / 256, 256>>>(X);
    dim3 grid_g(NN / 128, NN / 128);
    gemm_mma<<<grid_g, 256, 65536>>>();
    rowstats<<<NN, 256>>>();
    final_reduce<<<1, 256>>>(out);
}

// round 4
// speedup vs baseline: 1.8622x; 1.0663x over previous
#include <cuda_runtime.h>
#include <cuda_bf16.h>
#include <math.h>
#include <stdint.h>

#define NN 4096
#define DD 256
#define KK 8

// ---------------------------------------------------------------------------
// Scratch (static __device__, no allocs)
// ---------------------------------------------------------------------------
__device__ float g_sim[(size_t)NN * NN];                  // 64 MB
__device__ __nv_bfloat16 g_hi[(size_t)NN * DD];           // 2 MB
__device__ __nv_bfloat16 g_lo[(size_t)NN * DD];           // 2 MB
__device__ float4 g_row[NN];                              // per-row results
__device__ unsigned int g_cnt;                            // rowstats completion counter

// ---------------------------------------------------------------------------
// helpers
// ---------------------------------------------------------------------------
__device__ __forceinline__ uint32_t smem_u32(const void* p) {
    uint32_t a;
    asm("{ .reg .u64 t; cvta.to.shared.u64 t, %1; cvt.u32.u64 %0, t; }"
        : "=r"(a) : "l"(p));
    return a;
}
#define SWZ128(x) ((x) ^ (((x) >> 3) & 0x70))

__device__ __forceinline__ void cp_async16(uint32_t saddr, const void* gaddr) {
    asm volatile("cp.async.cg.shared.global [%0], [%1], 16;"
                 :: "r"(saddr), "l"(gaddr) : "memory");
}
#define CP_COMMIT() asm volatile("cp.async.commit_group;" ::: "memory")
#define CP_WAIT(n)  asm volatile("cp.async.wait_group %0;" :: "n"(n) : "memory")

__device__ __forceinline__ void ldmat_x4(uint32_t& r0, uint32_t& r1,
                                         uint32_t& r2, uint32_t& r3, uint32_t a) {
    asm volatile("ldmatrix.sync.aligned.m8n8.x4.shared.b16 {%0,%1,%2,%3}, [%4];"
                 : "=r"(r0), "=r"(r1), "=r"(r2), "=r"(r3) : "r"(a));
}

__device__ __forceinline__ void mma_bf16(float* c, const uint32_t* a, const uint32_t* b) {
    asm volatile("mma.sync.aligned.m16n8k16.row.col.f32.bf16.bf16.f32 "
                 "{%0,%1,%2,%3}, {%4,%5,%6,%7}, {%8,%9}, {%0,%1,%2,%3};"
                 : "+f"(c[0]), "+f"(c[1]), "+f"(c[2]), "+f"(c[3])
                 : "r"(a[0]), "r"(a[1]), "r"(a[2]), "r"(a[3]),
                   "r"(b[0]), "r"(b[1]));
}

// ---------------------------------------------------------------------------
// Kernel 0: bf16 hi/lo split
// ---------------------------------------------------------------------------
__global__ void __launch_bounds__(256) split_bf16(const float* __restrict__ X) {
    int i = blockIdx.x * 256 + threadIdx.x;
    float x = X[i];
    __nv_bfloat16 h = __float2bfloat16(x);
    g_hi[i] = h;
    g_lo[i] = __float2bfloat16(x - __bfloat162float(h));
}

// ---------------------------------------------------------------------------
// Kernel 1: symmetric bf16x3 GEMM via mma.sync (HMMA), cp.async double-buffer.
// CTA: 128x128 tile, 8 warps (2 x 4), warp tile 64x32. K = 3*256 logical.
// ---------------------------------------------------------------------------
extern __shared__ unsigned char dynsmem[];   // 64 KB: 2 x (16K A + 16K B)

__global__ void __launch_bounds__(256, 2) gemm_mma() {
    const int br = blockIdx.y, bc = blockIdx.x;
    if (bc < br) return;

    const int tid = threadIdx.x;
    const int wid = tid >> 5, lid = tid & 31;
    const int wr = wid >> 2, wc = wid & 3;      // 2 x 4 warp grid

    const uint32_t sbase = smem_u32(dynsmem);

    float acc[4][4][4];
    #pragma unroll
    for (int mi = 0; mi < 4; mi++)
        #pragma unroll
        for (int ni = 0; ni < 4; ni++)
            #pragma unroll
            for (int q = 0; q < 4; q++) acc[mi][ni][q] = 0.f;

    int lrow[4], lsg[4];
    uint32_t soff[4];
    #pragma unroll
    for (int it = 0; it < 4; it++) {
        int idx = tid + it * 256;
        lrow[it] = idx >> 3;
        lsg[it]  = idx & 7;
        soff[it] = SWZ128((uint32_t)(lrow[it] * 128 + lsg[it] * 16));
    }

    const __nv_bfloat16* Asrc[3] = { g_hi, g_hi, g_lo };
    const __nv_bfloat16* Bsrc[3] = { g_hi, g_lo, g_hi };

    auto issue = [&](int c) {
        const int seg = c >> 2, colb = (c & 3) * 64;
        const char* pa = (const char*)Asrc[seg];
        const char* pb = (const char*)Bsrc[seg];
        const uint32_t sb = sbase + (uint32_t)(c & 1) * 32768u;
        #pragma unroll
        for (int it = 0; it < 4; it++) {
            size_t ao = ((size_t)(br * 128 + lrow[it]) * DD + colb) * 2 + lsg[it] * 16;
            size_t bo = ((size_t)(bc * 128 + lrow[it]) * DD + colb) * 2 + lsg[it] * 16;
            cp_async16(sb + soff[it], pa + ao);
            cp_async16(sb + 16384u + soff[it], pb + bo);
        }
        CP_COMMIT();
    };

    issue(0);

    for (int c = 0; c < 12; c++) {
        if (c + 1 < 12) { issue(c + 1); CP_WAIT(1); }
        else            { CP_WAIT(0); }
        __syncthreads();

        const uint32_t sA = sbase + (uint32_t)(c & 1) * 32768u;
        const uint32_t sB = sA + 16384u;
        const int sub = lid >> 3;
        const int l8  = lid & 7;

        #pragma unroll
        for (int kk = 0; kk < 4; kk++) {
            const int kbase = kk * 16;
            uint32_t bfr[4][2];
            #pragma unroll
            for (int nj = 0; nj < 2; nj++) {
                int n  = wc * 32 + nj * 16 + l8 + (sub >> 1) * 8;
                int kh = kbase + (sub & 1) * 8;
                uint32_t addr = sB + SWZ128((uint32_t)(n * 128 + kh * 2));
                uint32_t r0, r1, r2, r3;
                ldmat_x4(r0, r1, r2, r3, addr);
                bfr[nj * 2 + 0][0] = r0; bfr[nj * 2 + 0][1] = r1;
                bfr[nj * 2 + 1][0] = r2; bfr[nj * 2 + 1][1] = r3;
            }
            #pragma unroll
            for (int mi = 0; mi < 4; mi++) {
                int r  = wr * 64 + mi * 16 + l8 + (sub & 1) * 8;
                int kh = kbase + (sub >> 1) * 8;
                uint32_t addr = sA + SWZ128((uint32_t)(r * 128 + kh * 2));
                uint32_t afr[4];
                ldmat_x4(afr[0], afr[1], afr[2], afr[3], addr);
                #pragma unroll
                for (int ni = 0; ni < 4; ni++)
                    mma_bf16(acc[mi][ni], afr, bfr[ni]);
            }
        }
        __syncthreads();
    }

    // ----- direct stores (upper-triangle tile, row-major) -----
    const int qr = lid >> 2, qc = lid & 3;
    #pragma unroll
    for (int mi = 0; mi < 4; mi++) {
        int row = br * 128 + wr * 64 + mi * 16 + qr;
        #pragma unroll
        for (int ni = 0; ni < 4; ni++) {
            int col = bc * 128 + wc * 32 + ni * 8 + 2 * qc;
            *(float2*)&g_sim[(size_t)row * NN + col] =
                make_float2(acc[mi][ni][0], acc[mi][ni][1]);
            *(float2*)&g_sim[(size_t)(row + 8) * NN + col] =
                make_float2(acc[mi][ni][2], acc[mi][ni][3]);
        }
    }

    // ----- mirror stores: two 64-col halves, all warps active, 64x132 staging
    if (bc > br) {
        float* tr = (float*)dynsmem;             // 64 x 132 fp32 = 33.8 KB
        #pragma unroll
        for (int h = 0; h < 2; h++) {
            __syncthreads();
            if ((wc >> 1) == h) {
                #pragma unroll
                for (int mi = 0; mi < 4; mi++) {
                    int r = wr * 64 + mi * 16 + qr;
                    #pragma unroll
                    for (int ni = 0; ni < 4; ni++) {
                        int j = (wc & 1) * 32 + ni * 8 + 2 * qc;   // col within half
                        tr[(size_t)j * 132 + r]           = acc[mi][ni][0];
                        tr[(size_t)(j + 1) * 132 + r]     = acc[mi][ni][1];
                        tr[(size_t)j * 132 + r + 8]       = acc[mi][ni][2];
                        tr[(size_t)(j + 1) * 132 + r + 8] = acc[mi][ni][3];
                    }
                }
            }
            __syncthreads();
            // store 64 mirror rows x 128 cols, coalesced
            for (int rr = wid; rr < 64; rr += 8) {
                int gr = bc * 128 + h * 64 + rr;
                float4 v = *(float4*)&tr[(size_t)rr * 132 + lid * 4];
                *(float4*)&g_sim[(size_t)gr * NN + br * 128 + lid * 4] = v;
            }
        }
    }
}

// ---------------------------------------------------------------------------
__device__ __forceinline__ float softplus_f(float z) {
    // max(z,0) + log(1+exp(-|z|)) with fast MUFU ops
    float e = __expf(-fabsf(z));
    return fmaxf(z, 0.f) + __logf(1.f + e);
}

__device__ __forceinline__ float block_red(float v, float* sh, bool is_min) {
    #pragma unroll
    for (int o = 16; o; o >>= 1) {
        float u = __shfl_xor_sync(0xffffffffu, v, o);
        v = is_min ? fminf(v, u) : (v + u);
    }
    int w = threadIdx.x >> 5, l = threadIdx.x & 31;
    __syncthreads();
    if (l == 0) sh[w] = v;
    __syncthreads();
    if (threadIdx.x < 32) {
        v = (l < 8) ? sh[l] : (is_min ? 1e30f : 0.f);
        #pragma unroll
        for (int o = 4; o; o >>= 1) {
            float u = __shfl_xor_sync(0xffffffffu, v, o);
            v = is_min ? fminf(v, u) : (v + u);
        }
        if (l == 0) sh[0] = v;
    }
    __syncthreads();
    return sh[0];
}

// ---------------------------------------------------------------------------
// Kernel 2: per-row stats + loss + fused final reduction (last-block pattern).
// ---------------------------------------------------------------------------
__global__ void __launch_bounds__(256) rowstats(float* __restrict__ out) {
    const int i   = blockIdx.x;
    const int tid = threadIdx.x;

    __shared__ float red[32];
    __shared__ float s_inter, s_th;
    __shared__ bool  s_last;

    float v[16];
    const float4* rp = (const float4*)&g_sim[(size_t)i * NN];
    #pragma unroll
    for (int q = 0; q < 4; q++) {
        float4 t = rp[tid + q * 256];
        v[q * 4 + 0] = t.x; v[q * 4 + 1] = t.y;
        v[q * 4 + 2] = t.z; v[q * 4 + 3] = t.w;
    }

    const int cls_lo = (i / KK) * KK;
    const int cls_hi = cls_lo + KK;

    float ps = 0.f, pq = 0.f, pmin = 1e30f, ns = 0.f, nq = 0.f;
    #pragma unroll
    for (int q = 0; q < 4; q++) {
        #pragma unroll
        for (int s = 0; s < 4; s++) {
            int j = (tid + q * 256) * 4 + s;
            float x = v[q * 4 + s];
            bool same = (j >= cls_lo) & (j < cls_hi);
            if (same) {
                if (j != i) { ps += x; pq += x * x; pmin = fminf(pmin, x); }
            } else {
                ns += x; nq += x * x;
            }
        }
    }
    ps   = block_red(ps, red, false);
    pq   = block_red(pq, red, false);
    ns   = block_red(ns, red, false);
    nq   = block_red(nq, red, false);
    pmin = block_red(pmin, red, true);

    if (tid == 0) {
        const float p = (float)(KK - 1);
        const float m = (float)(NN - KK);
        float pmean = ps / p, nmean = ns / m;
        float pvar = fmaxf(pq / p - pmean * pmean, 0.f);
        float nvar = fmaxf(nq / m - nmean * nmean, 0.f);
        float psd = sqrtf(pvar), nsd = sqrtf(nvar);
        s_inter = 0.8f * (nsd * pmean + psd * nmean) / (psd + nsd) + 0.1f;
        s_th    = pmin - 0.05f;
    }
    __syncthreads();
    const float inter = s_inter;
    const float th    = s_th;

    float psum = 0.f, nsum = 0.f, cntf = 0.f;
    #pragma unroll
    for (int q = 0; q < 4; q++) {
        #pragma unroll
        for (int s = 0; s < 4; s++) {
            int j = (tid + q * 256) * 4 + s;
            float x = v[q * 4 + s];
            bool same = (j >= cls_lo) & (j < cls_hi);
            if (same) {
                if (j != i) psum += softplus_f(-10.f * (x - inter));
            } else if (x > th) {
                cntf += 1.f;
                nsum += softplus_f(40.f * (x - inter));
            }
        }
    }
    psum = block_red(psum, red, false);
    nsum = block_red(nsum, red, false);
    cntf = block_red(cntf, red, false);

    if (tid == 0) {
        float loss = 0.f, invalid = 1.f;
        if (cntf > 0.f) {
            loss = 0.2f * psum / (float)(KK - 1) + 0.05f * nsum / cntf;
            invalid = 0.f;
        }
        g_row[i] = make_float4(loss, invalid, ps, ns);
        __threadfence();
        unsigned int done = atomicAdd(&g_cnt, 1u);
        s_last = (done == (unsigned)(NN - 1));
    }
    __syncthreads();

    // ----- last block: deterministic final reduction over all rows -----
    if (s_last) {
        __threadfence();
        float a0 = 0.f, a1 = 0.f, a2 = 0.f, a3 = 0.f;
        for (int r = tid; r < NN; r += 256) {
            float4 t = g_row[r];
            a0 += t.x; a1 += t.y; a2 += t.z; a3 += t.w;
        }
        a0 = block_red(a0, red, false);
        a1 = block_red(a1, red, false);
        a2 = block_red(a2, red, false);
        a3 = block_red(a3, red, false);
        if (tid == 0) {
            out[0] = a0 / (float)NN;
            out[1] = a1 / (float)NN;
            out[2] = a2 / ((float)(KK - 1) * (float)NN);
            out[3] = a3 / ((float)(NN - KK) * (float)NN);
            g_cnt = 0;                      // reset for next graph replay
        }
    }
}

// ---------------------------------------------------------------------------
extern "C" void kernel_launch(void* const* d_in, const int* in_sizes, int n_in,
                              void* d_out, int out_size) {
    const float* X = (const float*)d_in[0];
    float* out = (float*)d_out;

    static bool attr_set = false;
    if (!attr_set) {
        cudaFuncSetAttribute(gemm_mma, cudaFuncAttributeMaxDynamicSharedMemorySize, 65536);
        attr_set = true;
    }

    split_bf16<<<NN * DD / 256, 256>>>(X);
    dim3 grid_g(NN / 128, NN / 128);
    gemm_mma<<<grid_g, 256, 65536>>>();
    rowstats<<<NN, 256>>>(out);
}

// round 5
// speedup vs baseline: 1.9878x; 1.0675x over previous
#include <cuda_runtime.h>
#include <cuda_bf16.h>
#include <math.h>
#include <stdint.h>

#define NN 4096
#define DD 256
#define KK 8

// ---------------------------------------------------------------------------
// Scratch (static __device__, no allocs)
// ---------------------------------------------------------------------------
__device__ float g_sim[(size_t)NN * NN];                  // 64 MB
__device__ __nv_bfloat16 g_hi[(size_t)NN * DD];           // 2 MB
__device__ __nv_bfloat16 g_lo[(size_t)NN * DD];           // 2 MB
__device__ float4 g_row[NN];                              // per-row results
__device__ unsigned int g_cnt;                            // completion counter

// ---------------------------------------------------------------------------
// helpers
// ---------------------------------------------------------------------------
__device__ __forceinline__ uint32_t smem_u32(const void* p) {
    uint32_t a;
    asm("{ .reg .u64 t; cvta.to.shared.u64 t, %1; cvt.u32.u64 %0, t; }"
        : "=r"(a) : "l"(p));
    return a;
}
#define SWZ128(x) ((x) ^ (((x) >> 3) & 0x70))

__device__ __forceinline__ void cp_async16(uint32_t saddr, const void* gaddr) {
    asm volatile("cp.async.cg.shared.global [%0], [%1], 16;"
                 :: "r"(saddr), "l"(gaddr) : "memory");
}
#define CP_COMMIT() asm volatile("cp.async.commit_group;" ::: "memory")
#define CP_WAIT(n)  asm volatile("cp.async.wait_group %0;" :: "n"(n) : "memory")

__device__ __forceinline__ void ldmat_x4(uint32_t& r0, uint32_t& r1,
                                         uint32_t& r2, uint32_t& r3, uint32_t a) {
    asm volatile("ldmatrix.sync.aligned.m8n8.x4.shared.b16 {%0,%1,%2,%3}, [%4];"
                 : "=r"(r0), "=r"(r1), "=r"(r2), "=r"(r3) : "r"(a));
}

__device__ __forceinline__ void mma_bf16(float* c, const uint32_t* a, const uint32_t* b) {
    asm volatile("mma.sync.aligned.m16n8k16.row.col.f32.bf16.bf16.f32 "
                 "{%0,%1,%2,%3}, {%4,%5,%6,%7}, {%8,%9}, {%0,%1,%2,%3};"
                 : "+f"(c[0]), "+f"(c[1]), "+f"(c[2]), "+f"(c[3])
                 : "r"(a[0]), "r"(a[1]), "r"(a[2]), "r"(a[3]),
                   "r"(b[0]), "r"(b[1]));
}

// ---------------------------------------------------------------------------
// Kernel 0: bf16 hi/lo split, vectorized (8 elements / thread)
// ---------------------------------------------------------------------------
__global__ void __launch_bounds__(256) split_bf16(const float* __restrict__ X) {
    const int base = (blockIdx.x * 256 + threadIdx.x) * 2;   // float4 index
    const float4* X4 = (const float4*)X;
    __nv_bfloat162* H2 = (__nv_bfloat162*)g_hi;
    __nv_bfloat162* L2 = (__nv_bfloat162*)g_lo;
    #pragma unroll
    for (int q = 0; q < 2; q++) {
        float4 x = X4[base + q];
        __nv_bfloat16 h0 = __float2bfloat16(x.x), h1 = __float2bfloat16(x.y);
        __nv_bfloat16 h2 = __float2bfloat16(x.z), h3 = __float2bfloat16(x.w);
        __nv_bfloat16 l0 = __float2bfloat16(x.x - __bfloat162float(h0));
        __nv_bfloat16 l1 = __float2bfloat16(x.y - __bfloat162float(h1));
        __nv_bfloat16 l2 = __float2bfloat16(x.z - __bfloat162float(h2));
        __nv_bfloat16 l3 = __float2bfloat16(x.w - __bfloat162float(h3));
        H2[(base + q) * 2 + 0] = __nv_bfloat162(h0, h1);
        H2[(base + q) * 2 + 1] = __nv_bfloat162(h2, h3);
        L2[(base + q) * 2 + 0] = __nv_bfloat162(l0, l1);
        L2[(base + q) * 2 + 1] = __nv_bfloat162(l2, l3);
    }
}

// ---------------------------------------------------------------------------
// Kernel 1: symmetric bf16x3 GEMM, mma.sync + 3-stage cp.async pipeline.
// CTA: 128x128 tile, 8 warps (2 x 4), warp tile 64x32. K = 3*256 logical.
// ---------------------------------------------------------------------------
extern __shared__ unsigned char dynsmem[];   // 96 KB: 3 x (16K A + 16K B)

__global__ void __launch_bounds__(256, 2) gemm_mma() {
    const int br = blockIdx.y, bc = blockIdx.x;
    if (bc < br) return;

    const int tid = threadIdx.x;
    const int wid = tid >> 5, lid = tid & 31;
    const int wr = wid >> 2, wc = wid & 3;      // 2 x 4 warp grid

    const uint32_t sbase = smem_u32(dynsmem);

    float acc[4][4][4];
    #pragma unroll
    for (int mi = 0; mi < 4; mi++)
        #pragma unroll
        for (int ni = 0; ni < 4; ni++)
            #pragma unroll
            for (int q = 0; q < 4; q++) acc[mi][ni][q] = 0.f;

    int lrow[4], lsg[4];
    uint32_t soff[4];
    #pragma unroll
    for (int it = 0; it < 4; it++) {
        int idx = tid + it * 256;
        lrow[it] = idx >> 3;
        lsg[it]  = idx & 7;
        soff[it] = SWZ128((uint32_t)(lrow[it] * 128 + lsg[it] * 16));
    }

    const __nv_bfloat16* Asrc[3] = { g_hi, g_hi, g_lo };
    const __nv_bfloat16* Bsrc[3] = { g_hi, g_lo, g_hi };

    auto issue = [&](int c) {
        const int seg = c >> 2, colb = (c & 3) * 64;
        const char* pa = (const char*)Asrc[seg];
        const char* pb = (const char*)Bsrc[seg];
        const uint32_t sb = sbase + (uint32_t)(c % 3) * 32768u;
        #pragma unroll
        for (int it = 0; it < 4; it++) {
            size_t ao = ((size_t)(br * 128 + lrow[it]) * DD + colb) * 2 + lsg[it] * 16;
            size_t bo = ((size_t)(bc * 128 + lrow[it]) * DD + colb) * 2 + lsg[it] * 16;
            cp_async16(sb + soff[it], pa + ao);
            cp_async16(sb + 16384u + soff[it], pb + bo);
        }
        CP_COMMIT();
    };

    issue(0);
    issue(1);

    for (int c = 0; c < 12; c++) {
        if (c + 2 < 12) { CP_WAIT(1); }
        else if (c == 10) { CP_WAIT(1); }
        else { CP_WAIT(0); }
        __syncthreads();                 // buf c visible; compute of c-1 done
        if (c + 2 < 12) issue(c + 2);    // safe: buf (c+2)%3 last read at c-1

        const uint32_t sA = sbase + (uint32_t)(c % 3) * 32768u;
        const uint32_t sB = sA + 16384u;
        const int sub = lid >> 3;
        const int l8  = lid & 7;

        #pragma unroll
        for (int kk = 0; kk < 4; kk++) {
            const int kbase = kk * 16;
            uint32_t bfr[4][2];
            #pragma unroll
            for (int nj = 0; nj < 2; nj++) {
                int n  = wc * 32 + nj * 16 + l8 + (sub >> 1) * 8;
                int kh = kbase + (sub & 1) * 8;
                uint32_t addr = sB + SWZ128((uint32_t)(n * 128 + kh * 2));
                uint32_t r0, r1, r2, r3;
                ldmat_x4(r0, r1, r2, r3, addr);
                bfr[nj * 2 + 0][0] = r0; bfr[nj * 2 + 0][1] = r1;
                bfr[nj * 2 + 1][0] = r2; bfr[nj * 2 + 1][1] = r3;
            }
            #pragma unroll
            for (int mi = 0; mi < 4; mi++) {
                int r  = wr * 64 + mi * 16 + l8 + (sub & 1) * 8;
                int kh = kbase + (sub >> 1) * 8;
                uint32_t addr = sA + SWZ128((uint32_t)(r * 128 + kh * 2));
                uint32_t afr[4];
                ldmat_x4(afr[0], afr[1], afr[2], afr[3], addr);
                #pragma unroll
                for (int ni = 0; ni < 4; ni++)
                    mma_bf16(acc[mi][ni], afr, bfr[ni]);
            }
        }
    }
    __syncthreads();

    // ----- direct stores (upper-triangle tile, row-major) -----
    const int qr = lid >> 2, qc = lid & 3;
    #pragma unroll
    for (int mi = 0; mi < 4; mi++) {
        int row = br * 128 + wr * 64 + mi * 16 + qr;
        #pragma unroll
        for (int ni = 0; ni < 4; ni++) {
            int col = bc * 128 + wc * 32 + ni * 8 + 2 * qc;
            *(float2*)&g_sim[(size_t)row * NN + col] =
                make_float2(acc[mi][ni][0], acc[mi][ni][1]);
            *(float2*)&g_sim[(size_t)(row + 8) * NN + col] =
                make_float2(acc[mi][ni][2], acc[mi][ni][3]);
        }
    }

    // ----- mirror stores: two 64-col halves, all warps active -----
    if (bc > br) {
        float* tr = (float*)dynsmem;             // 64 x 132 fp32
        #pragma unroll
        for (int h = 0; h < 2; h++) {
            __syncthreads();
            if ((wc >> 1) == h) {
                #pragma unroll
                for (int mi = 0; mi < 4; mi++) {
                    int r = wr * 64 + mi * 16 + qr;
                    #pragma unroll
                    for (int ni = 0; ni < 4; ni++) {
                        int j = (wc & 1) * 32 + ni * 8 + 2 * qc;
                        tr[(size_t)j * 132 + r]           = acc[mi][ni][0];
                        tr[(size_t)(j + 1) * 132 + r]     = acc[mi][ni][1];
                        tr[(size_t)j * 132 + r + 8]       = acc[mi][ni][2];
                        tr[(size_t)(j + 1) * 132 + r + 8] = acc[mi][ni][3];
                    }
                }
            }
            __syncthreads();
            for (int rr = wid; rr < 64; rr += 8) {
                int gr = bc * 128 + h * 64 + rr;
                float4 v = *(float4*)&tr[(size_t)rr * 132 + lid * 4];
                *(float4*)&g_sim[(size_t)gr * NN + br * 128 + lid * 4] = v;
            }
        }
    }
}

// ---------------------------------------------------------------------------
__device__ __forceinline__ float softplus_f(float z) {
    float e = __expf(-fabsf(z));
    return fmaxf(z, 0.f) + __logf(1.f + e);
}

// fused 5-value reduction: v[0..3] sums, v[4] min. 2 barriers total.
__device__ __forceinline__ void block_red5(float* v, float* sh) {
    #pragma unroll
    for (int o = 16; o; o >>= 1) {
        #pragma unroll
        for (int k = 0; k < 4; k++) v[k] += __shfl_xor_sync(0xffffffffu, v[k], o);
        v[4] = fminf(v[4], __shfl_xor_sync(0xffffffffu, v[4], o));
    }
    int w = threadIdx.x >> 5, l = threadIdx.x & 31;
    if (l == 0) {
        #pragma unroll
        for (int k = 0; k < 5; k++) sh[w * 5 + k] = v[k];
    }
    __syncthreads();
    if (threadIdx.x < 32) {
        #pragma unroll
        for (int k = 0; k < 4; k++) v[k] = (l < 8) ? sh[l * 5 + k] : 0.f;
        v[4] = (l < 8) ? sh[l * 5 + 4] : 1e30f;
        #pragma unroll
        for (int o = 4; o; o >>= 1) {
            #pragma unroll
            for (int k = 0; k < 4; k++) v[k] += __shfl_xor_sync(0xffffffffu, v[k], o);
            v[4] = fminf(v[4], __shfl_xor_sync(0xffffffffu, v[4], o));
        }
        if (l == 0) {
            #pragma unroll
            for (int k = 0; k < 5; k++) sh[k] = v[k];
        }
    }
    __syncthreads();
    #pragma unroll
    for (int k = 0; k < 5; k++) v[k] = sh[k];
}

// fused sum-reduction of NV values. 2 barriers.
template <int NV>
__device__ __forceinline__ void block_redN(float* v, float* sh) {
    #pragma unroll
    for (int o = 16; o; o >>= 1)
        #pragma unroll
        for (int k = 0; k < NV; k++) v[k] += __shfl_xor_sync(0xffffffffu, v[k], o);
    int w = threadIdx.x >> 5, l = threadIdx.x & 31;
    if (l == 0) {
        #pragma unroll
        for (int k = 0; k < NV; k++) sh[w * NV + k] = v[k];
    }
    __syncthreads();
    if (threadIdx.x < 32) {
        #pragma unroll
        for (int k = 0; k < NV; k++) v[k] = (l < 8) ? sh[l * NV + k] : 0.f;
        #pragma unroll
        for (int o = 4; o; o >>= 1)
            #pragma unroll
            for (int k = 0; k < NV; k++) v[k] += __shfl_xor_sync(0xffffffffu, v[k], o);
        if (l == 0) {
            #pragma unroll
            for (int k = 0; k < NV; k++) sh[k] = v[k];
        }
    }
    __syncthreads();
    #pragma unroll
    for (int k = 0; k < NV; k++) v[k] = sh[k];
}

// ---------------------------------------------------------------------------
// Kernel 2: per-row stats + loss + fused final reduction (last-block pattern).
// ---------------------------------------------------------------------------
__global__ void __launch_bounds__(256) rowstats(float* __restrict__ out) {
    const int i   = blockIdx.x;
    const int tid = threadIdx.x;

    __shared__ float red[48];
    __shared__ bool  s_last;

    float v[16];
    const float4* rp = (const float4*)&g_sim[(size_t)i * NN];
    #pragma unroll
    for (int q = 0; q < 4; q++) {
        float4 t = rp[tid + q * 256];
        v[q * 4 + 0] = t.x; v[q * 4 + 1] = t.y;
        v[q * 4 + 2] = t.z; v[q * 4 + 3] = t.w;
    }

    const int cls_lo = (i / KK) * KK;
    const int cls_hi = cls_lo + KK;

    // pass 1: {ps, pq, ns, nq, pmin}
    float r5[5] = {0.f, 0.f, 0.f, 0.f, 1e30f};
    #pragma unroll
    for (int q = 0; q < 4; q++) {
        #pragma unroll
        for (int s = 0; s < 4; s++) {
            int j = (tid + q * 256) * 4 + s;
            float x = v[q * 4 + s];
            bool same = (j >= cls_lo) & (j < cls_hi);
            if (same) {
                if (j != i) { r5[0] += x; r5[1] += x * x; r5[4] = fminf(r5[4], x); }
            } else {
                r5[2] += x; r5[3] += x * x;
            }
        }
    }
    block_red5(r5, red);
    const float ps = r5[0], pq = r5[1], ns = r5[2], nq = r5[3], pmin = r5[4];

    const float p = (float)(KK - 1);
    const float m = (float)(NN - KK);
    float pmean = ps / p, nmean = ns / m;
    float pvar = fmaxf(pq / p - pmean * pmean, 0.f);
    float nvar = fmaxf(nq / m - nmean * nmean, 0.f);
    float psd = sqrtf(pvar), nsd = sqrtf(nvar);
    const float inter = 0.8f * (nsd * pmean + psd * nmean) / (psd + nsd) + 0.1f;
    const float th    = pmin - 0.05f;

    // pass 2: {psum, nsum, cnt}
    float r3[3] = {0.f, 0.f, 0.f};
    #pragma unroll
    for (int q = 0; q < 4; q++) {
        #pragma unroll
        for (int s = 0; s < 4; s++) {
            int j = (tid + q * 256) * 4 + s;
            float x = v[q * 4 + s];
            bool same = (j >= cls_lo) & (j < cls_hi);
            if (same) {
                if (j != i) r3[0] += softplus_f(-10.f * (x - inter));
            } else if (x > th) {
                r3[2] += 1.f;
                r3[1] += softplus_f(40.f * (x - inter));
            }
        }
    }
    block_redN<3>(r3, red);

    if (tid == 0) {
        float loss = 0.f, invalid = 1.f;
        if (r3[2] > 0.f) {
            loss = 0.2f * r3[0] / p + 0.05f * r3[1] / r3[2];
            invalid = 0.f;
        }
        g_row[i] = make_float4(loss, invalid, ps, ns);
        __threadfence();
        unsigned int done = atomicAdd(&g_cnt, 1u);
        s_last = (done == (unsigned)(NN - 1));
    }
    __syncthreads();

    if (s_last) {
        __threadfence();
        float a[4] = {0.f, 0.f, 0.f, 0.f};
        for (int r = tid; r < NN; r += 256) {
            float4 t = g_row[r];
            a[0] += t.x; a[1] += t.y; a[2] += t.z; a[3] += t.w;
        }
        block_redN<4>(a, red);
        if (tid == 0) {
            out[0] = a[0] / (float)NN;
            out[1] = a[1] / (float)NN;
            out[2] = a[2] / (p * (float)NN);
            out[3] = a[3] / (m * (float)NN);
            g_cnt = 0;                      // reset for next graph replay
        }
    }
}

// ---------------------------------------------------------------------------
extern "C" void kernel_launch(void* const* d_in, const int* in_sizes, int n_in,
                              void* d_out, int out_size) {
    const float* X = (const float*)d_in[0];
    float* out = (float*)d_out;

    static bool attr_set = false;
    if (!attr_set) {
        cudaFuncSetAttribute(gemm_mma, cudaFuncAttributeMaxDynamicSharedMemorySize, 98304);
        attr_set = true;
    }

    split_bf16<<<NN * DD / 2048, 256>>>(X);
    dim3 grid_g(NN / 128, NN / 128);
    gemm_mma<<<grid_g, 256, 98304>>>();
    rowstats<<<NN, 256>>>(out);
}

// round 6
// speedup vs baseline: 2.1042x; 1.0585x over previous
#include <cuda_runtime.h>
#include <cuda_bf16.h>
#include <math.h>
#include <stdint.h>

#define NN 4096
#define DD 256
#define KK 8

// ---------------------------------------------------------------------------
// Scratch (static __device__, no allocs)
// ---------------------------------------------------------------------------
__device__ float g_sim[(size_t)NN * NN];                  // 64 MB
__device__ __nv_bfloat16 g_hi[(size_t)NN * DD];           // 2 MB
__device__ __nv_bfloat16 g_lo[(size_t)NN * DD];           // 2 MB
__device__ float4 g_row[NN];                              // per-row results
__device__ unsigned int g_cnt;                            // completion counter

// ---------------------------------------------------------------------------
// helpers
// ---------------------------------------------------------------------------
__device__ __forceinline__ uint32_t smem_u32(const void* p) {
    uint32_t a;
    asm("{ .reg .u64 t; cvta.to.shared.u64 t, %1; cvt.u32.u64 %0, t; }"
        : "=r"(a) : "l"(p));
    return a;
}
#define SWZ128(x) ((x) ^ (((x) >> 3) & 0x70))

__device__ __forceinline__ void cp_async16(uint32_t saddr, const void* gaddr) {
    asm volatile("cp.async.cg.shared.global [%0], [%1], 16;"
                 :: "r"(saddr), "l"(gaddr) : "memory");
}
#define CP_COMMIT() asm volatile("cp.async.commit_group;" ::: "memory")
#define CP_WAIT(n)  asm volatile("cp.async.wait_group %0;" :: "n"(n) : "memory")

__device__ __forceinline__ void ldmat_x4(uint32_t& r0, uint32_t& r1,
                                         uint32_t& r2, uint32_t& r3, uint32_t a) {
    asm volatile("ldmatrix.sync.aligned.m8n8.x4.shared.b16 {%0,%1,%2,%3}, [%4];"
                 : "=r"(r0), "=r"(r1), "=r"(r2), "=r"(r3) : "r"(a));
}

__device__ __forceinline__ void mma_bf16(float* c, const uint32_t* a, const uint32_t* b) {
    asm volatile("mma.sync.aligned.m16n8k16.row.col.f32.bf16.bf16.f32 "
                 "{%0,%1,%2,%3}, {%4,%5,%6,%7}, {%8,%9}, {%0,%1,%2,%3};"
                 : "+f"(c[0]), "+f"(c[1]), "+f"(c[2]), "+f"(c[3])
                 : "r"(a[0]), "r"(a[1]), "r"(a[2]), "r"(a[3]),
                   "r"(b[0]), "r"(b[1]));
}

// ---------------------------------------------------------------------------
// Kernel 0: bf16 hi/lo split; 8 contiguous elems/thread, 16B packed stores.
// ---------------------------------------------------------------------------
__global__ void __launch_bounds__(256) split_bf16(const float* __restrict__ X) {
    const int gid = blockIdx.x * 256 + threadIdx.x;       // one uint4 (8 bf16)
    const float4* X4 = (const float4*)X;
    float4 a = X4[gid * 2 + 0];
    float4 b = X4[gid * 2 + 1];

    __nv_bfloat162 h01 = __float22bfloat162_rn(make_float2(a.x, a.y));
    __nv_bfloat162 h23 = __float22bfloat162_rn(make_float2(a.z, a.w));
    __nv_bfloat162 h45 = __float22bfloat162_rn(make_float2(b.x, b.y));
    __nv_bfloat162 h67 = __float22bfloat162_rn(make_float2(b.z, b.w));

    float2 f01 = __bfloat1622float2(h01), f23 = __bfloat1622float2(h23);
    float2 f45 = __bfloat1622float2(h45), f67 = __bfloat1622float2(h67);
    __nv_bfloat162 l01 = __float22bfloat162_rn(make_float2(a.x - f01.x, a.y - f01.y));
    __nv_bfloat162 l23 = __float22bfloat162_rn(make_float2(a.z - f23.x, a.w - f23.y));
    __nv_bfloat162 l45 = __float22bfloat162_rn(make_float2(b.x - f45.x, b.y - f45.y));
    __nv_bfloat162 l67 = __float22bfloat162_rn(make_float2(b.z - f67.x, b.w - f67.y));

    uint4 hv, lv;
    hv.x = *(uint32_t*)&h01; hv.y = *(uint32_t*)&h23;
    hv.z = *(uint32_t*)&h45; hv.w = *(uint32_t*)&h67;
    lv.x = *(uint32_t*)&l01; lv.y = *(uint32_t*)&l23;
    lv.z = *(uint32_t*)&l45; lv.w = *(uint32_t*)&l67;
    ((uint4*)g_hi)[gid] = hv;
    ((uint4*)g_lo)[gid] = lv;
}

// ---------------------------------------------------------------------------
// Kernel 1: symmetric bf16x3 GEMM, 4 warps, warp tile 64x64, 3-stage cp.async.
// CTA: 128x128 tile, warp grid 2x2. K = 3*256 logical in 12 chunks of 64.
// ---------------------------------------------------------------------------
extern __shared__ unsigned char dynsmem[];   // 96 KB: 3 x (16K A + 16K B)

__global__ void __launch_bounds__(128, 2) gemm_mma() {
    const int br = blockIdx.y, bc = blockIdx.x;
    if (bc < br) return;

    const int tid = threadIdx.x;
    const int wid = tid >> 5, lid = tid & 31;
    const int wr = wid >> 1, wc = wid & 1;      // 2 x 2 warp grid

    const uint32_t sbase = smem_u32(dynsmem);

    float acc[4][8][4];
    #pragma unroll
    for (int mi = 0; mi < 4; mi++)
        #pragma unroll
        for (int ni = 0; ni < 8; ni++)
            #pragma unroll
            for (int q = 0; q < 4; q++) acc[mi][ni][q] = 0.f;

    int lrow[8], lsg[8];
    uint32_t soff[8];
    #pragma unroll
    for (int it = 0; it < 8; it++) {
        int idx = tid + it * 128;
        lrow[it] = idx >> 3;
        lsg[it]  = idx & 7;
        soff[it] = SWZ128((uint32_t)(lrow[it] * 128 + lsg[it] * 16));
    }

    const __nv_bfloat16* Asrc[3] = { g_hi, g_hi, g_lo };
    const __nv_bfloat16* Bsrc[3] = { g_hi, g_lo, g_hi };

    auto issue = [&](int c) {
        const int seg = c >> 2, colb = (c & 3) * 64;
        const char* pa = (const char*)Asrc[seg];
        const char* pb = (const char*)Bsrc[seg];
        const uint32_t sb = sbase + (uint32_t)(c % 3) * 32768u;
        #pragma unroll
        for (int it = 0; it < 8; it++) {
            size_t ao = ((size_t)(br * 128 + lrow[it]) * DD + colb) * 2 + lsg[it] * 16;
            size_t bo = ((size_t)(bc * 128 + lrow[it]) * DD + colb) * 2 + lsg[it] * 16;
            cp_async16(sb + soff[it], pa + ao);
            cp_async16(sb + 16384u + soff[it], pb + bo);
        }
        CP_COMMIT();
    };

    issue(0);
    issue(1);

    for (int c = 0; c < 12; c++) {
        if (c + 2 < 12) { CP_WAIT(1); }
        else if (c == 10) { CP_WAIT(1); }
        else { CP_WAIT(0); }
        __syncthreads();
        if (c + 2 < 12) issue(c + 2);

        const uint32_t sA = sbase + (uint32_t)(c % 3) * 32768u;
        const uint32_t sB = sA + 16384u;
        const int sub = lid >> 3;
        const int l8  = lid & 7;

        #pragma unroll
        for (int kk = 0; kk < 4; kk++) {
            const int kbase = kk * 16;
            uint32_t bfr[8][2];
            #pragma unroll
            for (int nj = 0; nj < 4; nj++) {
                int n  = wc * 64 + nj * 16 + l8 + (sub >> 1) * 8;
                int kh = kbase + (sub & 1) * 8;
                uint32_t addr = sB + SWZ128((uint32_t)(n * 128 + kh * 2));
                uint32_t r0, r1, r2, r3;
                ldmat_x4(r0, r1, r2, r3, addr);
                bfr[nj * 2 + 0][0] = r0; bfr[nj * 2 + 0][1] = r1;
                bfr[nj * 2 + 1][0] = r2; bfr[nj * 2 + 1][1] = r3;
            }
            uint32_t afr[4][4];
            #pragma unroll
            for (int mi = 0; mi < 4; mi++) {
                int r  = wr * 64 + mi * 16 + l8 + (sub & 1) * 8;
                int kh = kbase + (sub >> 1) * 8;
                uint32_t addr = sA + SWZ128((uint32_t)(r * 128 + kh * 2));
                ldmat_x4(afr[mi][0], afr[mi][1], afr[mi][2], afr[mi][3], addr);
            }
            #pragma unroll
            for (int mi = 0; mi < 4; mi++)
                #pragma unroll
                for (int ni = 0; ni < 8; ni++)
                    mma_bf16(acc[mi][ni], afr[mi], bfr[ni]);
        }
    }
    __syncthreads();

    // ----- direct stores (upper-triangle tile, row-major) -----
    const int qr = lid >> 2, qc = lid & 3;
    #pragma unroll
    for (int mi = 0; mi < 4; mi++) {
        int row = br * 128 + wr * 64 + mi * 16 + qr;
        #pragma unroll
        for (int ni = 0; ni < 8; ni++) {
            int col = bc * 128 + wc * 64 + ni * 8 + 2 * qc;
            *(float2*)&g_sim[(size_t)row * NN + col] =
                make_float2(acc[mi][ni][0], acc[mi][ni][1]);
            *(float2*)&g_sim[(size_t)(row + 8) * NN + col] =
                make_float2(acc[mi][ni][2], acc[mi][ni][3]);
        }
    }

    // ----- mirror stores: two 64-col halves via 64x132 smem transpose -----
    if (bc > br) {
        float* tr = (float*)dynsmem;
        #pragma unroll
        for (int h = 0; h < 2; h++) {
            __syncthreads();
            if (wc == h) {                      // 2 warps stage (cover all 128 rows)
                #pragma unroll
                for (int mi = 0; mi < 4; mi++) {
                    int r = wr * 64 + mi * 16 + qr;
                    #pragma unroll
                    for (int ni = 0; ni < 8; ni++) {
                        int j = ni * 8 + 2 * qc;
                        tr[(size_t)j * 132 + r]           = acc[mi][ni][0];
                        tr[(size_t)(j + 1) * 132 + r]     = acc[mi][ni][1];
                        tr[(size_t)j * 132 + r + 8]       = acc[mi][ni][2];
                        tr[(size_t)(j + 1) * 132 + r + 8] = acc[mi][ni][3];
                    }
                }
            }
            __syncthreads();
            for (int rr = wid; rr < 64; rr += 4) {
                int gr = bc * 128 + h * 64 + rr;
                float4 v = *(float4*)&tr[(size_t)rr * 132 + lid * 4];
                *(float4*)&g_sim[(size_t)gr * NN + br * 128 + lid * 4] = v;
            }
        }
    }
}

// ---------------------------------------------------------------------------
__device__ __forceinline__ float softplus_f(float z) {
    float e = __expf(-fabsf(z));
    return fmaxf(z, 0.f) + __logf(1.f + e);
}

// fused 5-value reduction: v[0..3] sums, v[4] min. 2 barriers total.
__device__ __forceinline__ void block_red5(float* v, float* sh) {
    #pragma unroll
    for (int o = 16; o; o >>= 1) {
        #pragma unroll
        for (int k = 0; k < 4; k++) v[k] += __shfl_xor_sync(0xffffffffu, v[k], o);
        v[4] = fminf(v[4], __shfl_xor_sync(0xffffffffu, v[4], o));
    }
    int w = threadIdx.x >> 5, l = threadIdx.x & 31;
    if (l == 0) {
        #pragma unroll
        for (int k = 0; k < 5; k++) sh[w * 5 + k] = v[k];
    }
    __syncthreads();
    if (threadIdx.x < 32) {
        #pragma unroll
        for (int k = 0; k < 4; k++) v[k] = (l < 8) ? sh[l * 5 + k] : 0.f;
        v[4] = (l < 8) ? sh[l * 5 + 4] : 1e30f;
        #pragma unroll
        for (int o = 4; o; o >>= 1) {
            #pragma unroll
            for (int k = 0; k < 4; k++) v[k] += __shfl_xor_sync(0xffffffffu, v[k], o);
            v[4] = fminf(v[4], __shfl_xor_sync(0xffffffffu, v[4], o));
        }
        if (l == 0) {
            #pragma unroll
            for (int k = 0; k < 5; k++) sh[k] = v[k];
        }
    }
    __syncthreads();
    #pragma unroll
    for (int k = 0; k < 5; k++) v[k] = sh[k];
}

template <int NV>
__device__ __forceinline__ void block_redN(float* v, float* sh) {
    #pragma unroll
    for (int o = 16; o; o >>= 1)
        #pragma unroll
        for (int k = 0; k < NV; k++) v[k] += __shfl_xor_sync(0xffffffffu, v[k], o);
    int w = threadIdx.x >> 5, l = threadIdx.x & 31;
    if (l == 0) {
        #pragma unroll
        for (int k = 0; k < NV; k++) sh[w * NV + k] = v[k];
    }
    __syncthreads();
    if (threadIdx.x < 32) {
        #pragma unroll
        for (int k = 0; k < NV; k++) v[k] = (l < 8) ? sh[l * NV + k] : 0.f;
        #pragma unroll
        for (int o = 4; o; o >>= 1)
            #pragma unroll
            for (int k = 0; k < NV; k++) v[k] += __shfl_xor_sync(0xffffffffu, v[k], o);
        if (l == 0) {
            #pragma unroll
            for (int k = 0; k < NV; k++) sh[k] = v[k];
        }
    }
    __syncthreads();
    #pragma unroll
    for (int k = 0; k < NV; k++) v[k] = sh[k];
}

// ---------------------------------------------------------------------------
// Kernel 2: per-row stats + loss + fused final reduction (last-block pattern).
// Class window is 8-aligned -> every aligned float4 group is fully in or out.
// ---------------------------------------------------------------------------
__global__ void __launch_bounds__(256) rowstats(float* __restrict__ out) {
    const int i   = blockIdx.x;
    const int tid = threadIdx.x;

    __shared__ float red[48];
    __shared__ bool  s_last;

    float v[16];
    const float4* rp = (const float4*)&g_sim[(size_t)i * NN];
    #pragma unroll
    for (int q = 0; q < 4; q++) {
        float4 t = rp[tid + q * 256];
        v[q * 4 + 0] = t.x; v[q * 4 + 1] = t.y;
        v[q * 4 + 2] = t.z; v[q * 4 + 3] = t.w;
    }

    const int cls_lo = (i / KK) * KK;

    // pass 1: {ps, pq, ns, nq, pmin}
    float r5[5] = {0.f, 0.f, 0.f, 0.f, 1e30f};
    #pragma unroll
    for (int q = 0; q < 4; q++) {
        const int j0 = (tid + q * 256) * 4;
        const bool gin = ((unsigned)(j0 - cls_lo) < (unsigned)KK);
        float x0 = v[q*4+0], x1 = v[q*4+1], x2 = v[q*4+2], x3 = v[q*4+3];
        if (!gin) {
            r5[2] += (x0 + x1) + (x2 + x3);
            r5[3] += (x0*x0 + x1*x1) + (x2*x2 + x3*x3);
        } else {
            #pragma unroll
            for (int s = 0; s < 4; s++) {
                float x = v[q * 4 + s];
                if (j0 + s != i) { r5[0] += x; r5[1] += x * x; r5[4] = fminf(r5[4], x); }
            }
        }
    }
    block_red5(r5, red);
    const float ps = r5[0], ns = r5[2];

    const float p = (float)(KK - 1);
    const float m = (float)(NN - KK);
    float pmean = ps / p, nmean = ns / m;
    float pvar = fmaxf(r5[1] / p - pmean * pmean, 0.f);
    float nvar = fmaxf(r5[3] / m - nmean * nmean, 0.f);
    float psd = sqrtf(pvar), nsd = sqrtf(nvar);
    const float inter = 0.8f * (nsd * pmean + psd * nmean) / (psd + nsd) + 0.1f;
    const float th    = r5[4] - 0.05f;

    // pass 2: {psum, nsum, cnt}
    float r3[3] = {0.f, 0.f, 0.f};
    #pragma unroll
    for (int q = 0; q < 4; q++) {
        const int j0 = (tid + q * 256) * 4;
        const bool gin = ((unsigned)(j0 - cls_lo) < (unsigned)KK);
        if (!gin) {
            #pragma unroll
            for (int s = 0; s < 4; s++) {
                float x = v[q * 4 + s];
                if (x > th) {
                    r3[2] += 1.f;
                    r3[1] += softplus_f(40.f * (x - inter));
                }
            }
        } else {
            #pragma unroll
            for (int s = 0; s < 4; s++) {
                float x = v[q * 4 + s];
                if (j0 + s != i) r3[0] += softplus_f(-10.f * (x - inter));
            }
        }
    }
    block_redN<3>(r3, red);

    if (tid == 0) {
        float loss = 0.f, invalid = 1.f;
        if (r3[2] > 0.f) {
            loss = 0.2f * r3[0] / p + 0.05f * r3[1] / r3[2];
            invalid = 0.f;
        }
        g_row[i] = make_float4(loss, invalid, ps, ns);
        __threadfence();
        unsigned int done = atomicAdd(&g_cnt, 1u);
        s_last = (done == (unsigned)(NN - 1));
    }
    __syncthreads();

    if (s_last) {
        __threadfence();
        float a[4] = {0.f, 0.f, 0.f, 0.f};
        for (int r = tid; r < NN; r += 256) {
            float4 t = g_row[r];
            a[0] += t.x; a[1] += t.y; a[2] += t.z; a[3] += t.w;
        }
        block_redN<4>(a, red);
        if (tid == 0) {
            out[0] = a[0] / (float)NN;
            out[1] = a[1] / (float)NN;
            out[2] = a[2] / (p * (float)NN);
            out[3] = a[3] / (m * (float)NN);
            g_cnt = 0;                      // reset for next graph replay
        }
    }
}

// ---------------------------------------------------------------------------
extern "C" void kernel_launch(void* const* d_in, const int* in_sizes, int n_in,
                              void* d_out, int out_size) {
    const float* X = (const float*)d_in[0];
    float* out = (float*)d_out;

    static bool attr_set = false;
    if (!attr_set) {
        cudaFuncSetAttribute(gemm_mma, cudaFuncAttributeMaxDynamicSharedMemorySize, 98304);
        attr_set = true;
    }

    split_bf16<<<NN * DD / 2048, 256>>>(X);
    dim3 grid_g(NN / 128, NN / 128);
    gemm_mma<<<grid_g, 128, 98304>>>();
    rowstats<<<NN, 256>>>(out);
}